// round 1
// baseline (speedup 1.0000x reference)
#include <cuda_runtime.h>
#include <cuda_bf16.h>
#include <cstdint>

#define B_ 16
#define T_ 256
#define H_ 128
#define E_ 128
#define V_ 50000
#define G_ 512          // 4*H
#define M_ 4096         // B*T

// Scratch (no cudaMalloc allowed)
__device__ float g_xp[M_ * G_];   // x-projection for current layer [row][512], row = b*T+t
__device__ float g_y0[M_ * H_];   // layer-0 output
__device__ float g_y1[M_ * H_];   // layer-1 output

typedef unsigned long long ull;

__device__ __forceinline__ ull fma2(ull a, ull b, ull c) {
    ull d;
    asm("fma.rn.f32x2 %0, %1, %2, %3;" : "=l"(d) : "l"(a), "l"(b), "l"(c));
    return d;
}
__device__ __forceinline__ ull pack2(float lo, float hi) {
    ull d;
    asm("mov.b64 %0, {%1, %2};" : "=l"(d) : "f"(lo), "f"(hi));
    return d;
}
__device__ __forceinline__ float2 unpack2(ull v) {
    float2 r;
    asm("mov.b64 {%0, %1}, %2;" : "=f"(r.x), "=f"(r.y) : "l"(v));
    return r;
}

// ---------------------------------------------------------------------------
// Projection GEMM: C[M_,512] = A[M_,128] @ W[512,128]^T + (bia + bib)
// GATHER=true: A row m = emb[x[m]]
// Tiles 64x64, K=128 in two 64-chunks, 256 threads, 4x4 microtile.
// ---------------------------------------------------------------------------
template<bool GATHER>
__global__ __launch_bounds__(256)
void proj_kernel(const float* __restrict__ A, const int* __restrict__ xidx,
                 const float* __restrict__ emb, const float* __restrict__ W,
                 const float* __restrict__ bia, const float* __restrict__ bib,
                 float* __restrict__ C)
{
    __shared__ float As[64][64];   // [k][m]
    __shared__ float Bs[64][64];   // [k][n]
    const int tid = threadIdx.x;
    const int tx = tid & 15, ty = tid >> 4;
    const int m0 = blockIdx.y * 64, n0 = blockIdx.x * 64;
    const int l  = tid & 63;
    const int kq = tid >> 6;       // 0..3

    const float* arow;
    if (GATHER) arow = emb + (size_t)xidx[m0 + l] * E_;
    else        arow = A   + (size_t)(m0 + l) * H_;
    const float* brow = W + (size_t)(n0 + l) * H_;

    float acc[4][4] = {};

    for (int kc = 0; kc < 128; kc += 64) {
        __syncthreads();
        #pragma unroll
        for (int it = 0; it < 4; it++) {
            int kb = kq * 4 + it * 16;
            float4 va = *(const float4*)(arow + kc + kb);
            As[kb+0][l] = va.x; As[kb+1][l] = va.y; As[kb+2][l] = va.z; As[kb+3][l] = va.w;
            float4 vb = *(const float4*)(brow + kc + kb);
            Bs[kb+0][l] = vb.x; Bs[kb+1][l] = vb.y; Bs[kb+2][l] = vb.z; Bs[kb+3][l] = vb.w;
        }
        __syncthreads();
        #pragma unroll 16
        for (int k = 0; k < 64; k++) {
            float4 a4 = *(const float4*)&As[k][ty * 4];
            float4 b4 = *(const float4*)&Bs[k][tx * 4];
            float av[4] = {a4.x, a4.y, a4.z, a4.w};
            float bv[4] = {b4.x, b4.y, b4.z, b4.w};
            #pragma unroll
            for (int i = 0; i < 4; i++)
                #pragma unroll
                for (int j = 0; j < 4; j++)
                    acc[i][j] = fmaf(av[i], bv[j], acc[i][j]);
        }
    }

    #pragma unroll
    for (int i = 0; i < 4; i++) {
        int m = m0 + ty * 4 + i;
        #pragma unroll
        for (int j = 0; j < 4; j++) {
            int n = n0 + tx * 4 + j;
            C[(size_t)m * G_ + n] = acc[i][j] + bia[n] + bib[n];
        }
    }
}

// ---------------------------------------------------------------------------
// LSTM recurrence: one block per batch element, 512 threads (one per gate row).
// W_hh row split: K[0:64) in registers (32 x f32x2), K[64:128) in smem (pad 68).
// ---------------------------------------------------------------------------
#define WS_STRIDE 68
#define LSTM_SMEM ((G_ * WS_STRIDE + H_ + G_) * (int)sizeof(float))

__global__ __launch_bounds__(512, 1)
void lstm_kernel(const float* __restrict__ xp, const float* __restrict__ Whh,
                 float* __restrict__ y, float* __restrict__ hc_out, int layer)
{
    extern __shared__ float sm[];
    float* Ws      = sm;                        // [512][68] (cols 0..63 = W[g][64..127])
    float* h_s     = sm + G_ * WS_STRIDE;       // [128]
    float* gates_s = h_s + H_;                  // [512]

    const int g = threadIdx.x;
    const int b = blockIdx.x;
    const int gtype = g >> 7;                   // 0:i 1:f 2:g~ 3:o

    // Register half of W_hh row g: k in [0,64)
    ull w2[32];
    const ull* wp = (const ull*)(Whh + (size_t)g * H_);
    #pragma unroll
    for (int i = 0; i < 32; i++) w2[i] = wp[i];

    // Smem half: k in [64,128)
    float* wsrow = Ws + g * WS_STRIDE;
    const float* wh = Whh + (size_t)g * H_ + 64;
    #pragma unroll
    for (int i = 0; i < 16; i++)
        *(float4*)(wsrow + i * 4) = *(const float4*)(wh + i * 4);

    float c = 0.f;
    if (g < H_) h_s[g] = 0.f;
    __syncthreads();

    const float* xpb = xp + (size_t)b * T_ * G_ + g;
    float* yb = y + (size_t)b * T_ * H_;

    for (int t = 0; t < T_; t++) {
        float xv = __ldg(xpb + (size_t)t * G_);

        ull acc2 = 0;  // (0.f, 0.f)
        const ulonglong2* hp  = (const ulonglong2*)h_s;
        const ulonglong2* wp2 = (const ulonglong2*)wsrow;
        #pragma unroll
        for (int i = 0; i < 16; i++) {
            ulonglong2 hv = hp[i];                 // h[4i .. 4i+3], broadcast
            acc2 = fma2(w2[2*i],   hv.x, acc2);
            acc2 = fma2(w2[2*i+1], hv.y, acc2);
        }
        #pragma unroll
        for (int i = 0; i < 16; i++) {
            ulonglong2 hv = hp[16 + i];            // h[64+4i ..]
            ulonglong2 wv = wp2[i];                // conflict-free (stride 68)
            acc2 = fma2(wv.x, hv.x, acc2);
            acc2 = fma2(wv.y, hv.y, acc2);
        }
        float2 p = unpack2(acc2);
        float raw = p.x + p.y + xv;

        float act;
        if (gtype == 2) act = tanhf(raw);
        else            act = 1.0f / (1.0f + __expf(-raw));
        gates_s[g] = act;
        __syncthreads();

        if (g < H_) {
            float iv = gates_s[g];
            float fv = gates_s[H_ + g];
            float gv = gates_s[2 * H_ + g];
            float ov = gates_s[3 * H_ + g];
            c = fv * c + iv * gv;
            float hnew = ov * tanhf(c);
            h_s[g] = hnew;
            yb[(size_t)t * H_ + g] = hnew;
        }
        __syncthreads();
    }

    if (g < H_) {
        // d_out tail: h [2,B,H] then c [2,B,H]
        hc_out[(size_t)layer * (B_ * H_) + b * H_ + g]       = h_s[g];
        hc_out[(size_t)(2 + layer) * (B_ * H_) + b * H_ + g] = c;
    }
}

// ---------------------------------------------------------------------------
// FC GEMM: logits[M_,V_] = y1 @ fc_w^T + fc_b, packed-f32x2 microkernel.
// Tiles 64x64, K=128 in two 64-chunks, 256 threads, 4x4 microtile.
// ---------------------------------------------------------------------------
__global__ __launch_bounds__(256)
void fc_kernel(const float* __restrict__ A, const float* __restrict__ W,
               const float* __restrict__ bias, float* __restrict__ C)
{
    __shared__ float As[64][64];
    __shared__ float Bs[64][64];
    const int tid = threadIdx.x;
    const int tx = tid & 15, ty = tid >> 4;
    const int m0 = blockIdx.y * 64, n0 = blockIdx.x * 64;
    const int l  = tid & 63;
    const int kq = tid >> 6;

    const float* arow = A + (size_t)(m0 + l) * H_;
    const int nrow = n0 + l;
    const bool bvalid = nrow < V_;
    const float* brow = W + (size_t)(bvalid ? nrow : 0) * H_;

    ull acc[4][2];
    #pragma unroll
    for (int i = 0; i < 4; i++) { acc[i][0] = 0; acc[i][1] = 0; }

    for (int kc = 0; kc < 128; kc += 64) {
        __syncthreads();
        #pragma unroll
        for (int it = 0; it < 4; it++) {
            int kb = kq * 4 + it * 16;
            float4 va = *(const float4*)(arow + kc + kb);
            As[kb+0][l] = va.x; As[kb+1][l] = va.y; As[kb+2][l] = va.z; As[kb+3][l] = va.w;
            float4 vb = bvalid ? *(const float4*)(brow + kc + kb) : make_float4(0.f,0.f,0.f,0.f);
            Bs[kb+0][l] = vb.x; Bs[kb+1][l] = vb.y; Bs[kb+2][l] = vb.z; Bs[kb+3][l] = vb.w;
        }
        __syncthreads();
        #pragma unroll 16
        for (int k = 0; k < 64; k++) {
            float4 a4 = *(const float4*)&As[k][ty * 4];
            ulonglong2 b2 = *(const ulonglong2*)&Bs[k][tx * 4];  // pairs (n0,n1),(n2,n3)
            ull ad0 = pack2(a4.x, a4.x);
            ull ad1 = pack2(a4.y, a4.y);
            ull ad2 = pack2(a4.z, a4.z);
            ull ad3 = pack2(a4.w, a4.w);
            acc[0][0] = fma2(ad0, b2.x, acc[0][0]); acc[0][1] = fma2(ad0, b2.y, acc[0][1]);
            acc[1][0] = fma2(ad1, b2.x, acc[1][0]); acc[1][1] = fma2(ad1, b2.y, acc[1][1]);
            acc[2][0] = fma2(ad2, b2.x, acc[2][0]); acc[2][1] = fma2(ad2, b2.y, acc[2][1]);
            acc[3][0] = fma2(ad3, b2.x, acc[3][0]); acc[3][1] = fma2(ad3, b2.y, acc[3][1]);
        }
    }

    const int nb = n0 + tx * 4;
    if (nb >= V_) return;               // V%4==0, nb%4==0 -> whole float4 in/out
    float4 bv = *(const float4*)(bias + nb);
    #pragma unroll
    for (int i = 0; i < 4; i++) {
        int m = m0 + ty * 4 + i;
        float2 p0 = unpack2(acc[i][0]);
        float2 p1 = unpack2(acc[i][1]);
        float4 o = make_float4(p0.x + bv.x, p0.y + bv.y, p1.x + bv.z, p1.y + bv.w);
        *(float4*)(C + (size_t)m * V_ + nb) = o;
    }
}

// ---------------------------------------------------------------------------
extern "C" void kernel_launch(void* const* d_in, const int* in_sizes, int n_in,
                              void* d_out, int out_size)
{
    const int*   x     = (const int*)  d_in[0];
    const float* emb   = (const float*)d_in[1];
    const float* W_ih0 = (const float*)d_in[2];
    const float* W_hh0 = (const float*)d_in[3];
    const float* b_ih0 = (const float*)d_in[4];
    const float* b_hh0 = (const float*)d_in[5];
    const float* W_ih1 = (const float*)d_in[6];
    const float* W_hh1 = (const float*)d_in[7];
    const float* b_ih1 = (const float*)d_in[8];
    const float* b_hh1 = (const float*)d_in[9];
    const float* fc_w  = (const float*)d_in[10];
    const float* fc_b  = (const float*)d_in[11];
    float* out = (float*)d_out;

    float *xp, *y0, *y1;
    cudaGetSymbolAddress((void**)&xp, g_xp);
    cudaGetSymbolAddress((void**)&y0, g_y0);
    cudaGetSymbolAddress((void**)&y1, g_y1);

    cudaFuncSetAttribute(lstm_kernel, cudaFuncAttributeMaxDynamicSharedMemorySize, LSTM_SMEM);

    float* hc = out + (size_t)M_ * V_;   // logits first, then h[2,B,H], c[2,B,H]

    // Layer 0: x-projection (embedding gather fused) then recurrence
    proj_kernel<true><<<dim3(G_/64, M_/64), 256>>>(nullptr, x, emb, W_ih0, b_ih0, b_hh0, xp);
    lstm_kernel<<<B_, 512, LSTM_SMEM>>>(xp, W_hh0, y0, hc, 0);

    // Layer 1
    proj_kernel<false><<<dim3(G_/64, M_/64), 256>>>(y0, nullptr, nullptr, W_ih1, b_ih1, b_hh1, xp);
    lstm_kernel<<<B_, 512, LSTM_SMEM>>>(xp, W_hh1, y1, hc, 1);

    // Vocab projection
    fc_kernel<<<dim3((V_ + 63) / 64, M_ / 64), 256>>>(y1, fc_w, fc_b, out);
}

// round 8
// speedup vs baseline: 2.1907x; 2.1907x over previous
#include <cuda_runtime.h>
#include <cuda_bf16.h>
#include <cstdint>

#define B_ 16
#define T_ 256
#define H_ 128
#define E_ 128
#define V_ 50000
#define G_ 512          // 4*H
#define M_ 4096         // B*T

typedef unsigned long long ull;

// ---------------- scratch (no cudaMalloc allowed) ----------------
__device__ float g_xp[M_ * G_];
__device__ float g_y0[M_ * H_];
__device__ float g_y1[M_ * H_];
__device__ __nv_bfloat16 g_Whi[(size_t)V_ * H_];
__device__ __nv_bfloat16 g_Wlo[(size_t)V_ * H_];
__device__ __nv_bfloat16 g_Ahi[M_ * H_];
__device__ __nv_bfloat16 g_Alo[M_ * H_];

// ---------------- f32x2 helpers ----------------
__device__ __forceinline__ ull fma2(ull a, ull b, ull c) {
    ull d; asm("fma.rn.f32x2 %0, %1, %2, %3;" : "=l"(d) : "l"(a), "l"(b), "l"(c)); return d;
}
__device__ __forceinline__ ull add2(ull a, ull b) {
    ull d; asm("add.rn.f32x2 %0, %1, %2;" : "=l"(d) : "l"(a), "l"(b)); return d;
}
__device__ __forceinline__ float2 unpack2(ull v) {
    float2 r; asm("mov.b64 {%0, %1}, %2;" : "=f"(r.x), "=f"(r.y) : "l"(v)); return r;
}

// ---------------- Ampere-path tensor helpers (valid on compute_103) --------
__device__ __forceinline__ uint32_t smem_u32(const void* p) {
    uint32_t a;
    asm("{ .reg .u64 t; cvta.to.shared.u64 t, %1; cvt.u32.u64 %0, t; }" : "=r"(a) : "l"(p));
    return a;
}
__device__ __forceinline__ void cpasync16(uint32_t dst, const void* src) {
    asm volatile("cp.async.cg.shared.global [%0], [%1], 16;" :: "r"(dst), "l"(src));
}
#define CP_COMMIT() asm volatile("cp.async.commit_group;" ::: "memory")
#define CP_WAIT(n)  asm volatile("cp.async.wait_group %0;" :: "n"(n) : "memory")

__device__ __forceinline__ void ldsm_x4(uint32_t& r0, uint32_t& r1, uint32_t& r2, uint32_t& r3,
                                        uint32_t addr) {
    asm volatile("ldmatrix.sync.aligned.m8n8.x4.shared.b16 {%0,%1,%2,%3}, [%4];"
                 : "=r"(r0), "=r"(r1), "=r"(r2), "=r"(r3) : "r"(addr));
}
__device__ __forceinline__ void mma_bf16(float* c, const uint32_t* a, const uint32_t* b) {
    asm volatile(
        "mma.sync.aligned.m16n8k16.row.col.f32.bf16.bf16.f32 "
        "{%0,%1,%2,%3}, {%4,%5,%6,%7}, {%8,%9}, {%0,%1,%2,%3};"
        : "+f"(c[0]), "+f"(c[1]), "+f"(c[2]), "+f"(c[3])
        : "r"(a[0]), "r"(a[1]), "r"(a[2]), "r"(a[3]), "r"(b[0]), "r"(b[1]));
}

// ---------------------------------------------------------------------------
// hi/lo bf16 split conversion (vectorized x4)
// ---------------------------------------------------------------------------
__global__ __launch_bounds__(256)
void cvt_hilo(const float4* __restrict__ src, ushort4* __restrict__ hi,
              ushort4* __restrict__ lo, int n4)
{
    int i = blockIdx.x * 256 + threadIdx.x;
    if (i >= n4) return;
    float4 v = src[i];
    ushort4 h, l;
    {
        __nv_bfloat16 hb;
        hb = __float2bfloat16(v.x); h.x = __bfloat16_as_ushort(hb);
        l.x = __bfloat16_as_ushort(__float2bfloat16(v.x - __bfloat162float(hb)));
        hb = __float2bfloat16(v.y); h.y = __bfloat16_as_ushort(hb);
        l.y = __bfloat16_as_ushort(__float2bfloat16(v.y - __bfloat162float(hb)));
        hb = __float2bfloat16(v.z); h.z = __bfloat16_as_ushort(hb);
        l.z = __bfloat16_as_ushort(__float2bfloat16(v.z - __bfloat162float(hb)));
        hb = __float2bfloat16(v.w); h.w = __bfloat16_as_ushort(hb);
        l.w = __bfloat16_as_ushort(__float2bfloat16(v.w - __bfloat162float(hb)));
    }
    hi[i] = h;
    lo[i] = l;
}

// ---------------------------------------------------------------------------
// Projection GEMM: C[M_,512] = A @ W^T + bias
// ---------------------------------------------------------------------------
template<bool GATHER>
__global__ __launch_bounds__(256)
void proj_kernel(const float* __restrict__ A, const int* __restrict__ xidx,
                 const float* __restrict__ emb, const float* __restrict__ W,
                 const float* __restrict__ bia, const float* __restrict__ bib,
                 float* __restrict__ C)
{
    __shared__ float As[64][64];
    __shared__ float Bs[64][64];
    const int tid = threadIdx.x;
    const int tx = tid & 15, ty = tid >> 4;
    const int m0 = blockIdx.y * 64, n0 = blockIdx.x * 64;
    const int l  = tid & 63;
    const int kq = tid >> 6;

    const float* arow;
    if (GATHER) arow = emb + (size_t)xidx[m0 + l] * E_;
    else        arow = A   + (size_t)(m0 + l) * H_;
    const float* brow = W + (size_t)(n0 + l) * H_;

    float acc[4][4] = {};
    for (int kc = 0; kc < 128; kc += 64) {
        __syncthreads();
        #pragma unroll
        for (int it = 0; it < 4; it++) {
            int kb = kq * 4 + it * 16;
            float4 va = *(const float4*)(arow + kc + kb);
            As[kb+0][l] = va.x; As[kb+1][l] = va.y; As[kb+2][l] = va.z; As[kb+3][l] = va.w;
            float4 vb = *(const float4*)(brow + kc + kb);
            Bs[kb+0][l] = vb.x; Bs[kb+1][l] = vb.y; Bs[kb+2][l] = vb.z; Bs[kb+3][l] = vb.w;
        }
        __syncthreads();
        #pragma unroll 16
        for (int k = 0; k < 64; k++) {
            float4 a4 = *(const float4*)&As[k][ty * 4];
            float4 b4 = *(const float4*)&Bs[k][tx * 4];
            float av[4] = {a4.x, a4.y, a4.z, a4.w};
            float bv[4] = {b4.x, b4.y, b4.z, b4.w};
            #pragma unroll
            for (int i = 0; i < 4; i++)
                #pragma unroll
                for (int j = 0; j < 4; j++)
                    acc[i][j] = fmaf(av[i], bv[j], acc[i][j]);
        }
    }
    #pragma unroll
    for (int i = 0; i < 4; i++) {
        int m = m0 + ty * 4 + i;
        #pragma unroll
        for (int j = 0; j < 4; j++) {
            int n = n0 + tx * 4 + j;
            C[(size_t)m * G_ + n] = acc[i][j] + bia[n] + bib[n];
        }
    }
}

// ---------------------------------------------------------------------------
// LSTM recurrence (4 independent accumulators)
// ---------------------------------------------------------------------------
#define WS_STRIDE 68
#define LSTM_SMEM ((G_ * WS_STRIDE + H_ + G_) * (int)sizeof(float))

__global__ __launch_bounds__(512, 1)
void lstm_kernel(const float* __restrict__ xp, const float* __restrict__ Whh,
                 float* __restrict__ y, float* __restrict__ hc_out, int layer)
{
    extern __shared__ float sm[];
    float* Ws      = sm;
    float* h_s     = sm + G_ * WS_STRIDE;
    float* gates_s = h_s + H_;

    const int g = threadIdx.x;
    const int b = blockIdx.x;
    const int gtype = g >> 7;

    ull w2[32];
    const ull* wp = (const ull*)(Whh + (size_t)g * H_);
    #pragma unroll
    for (int i = 0; i < 32; i++) w2[i] = wp[i];

    float* wsrow = Ws + g * WS_STRIDE;
    const float* wh = Whh + (size_t)g * H_ + 64;
    #pragma unroll
    for (int i = 0; i < 16; i++)
        *(float4*)(wsrow + i * 4) = *(const float4*)(wh + i * 4);

    float c = 0.f;
    if (g < H_) h_s[g] = 0.f;
    __syncthreads();

    const float* xpb = xp + (size_t)b * T_ * G_ + g;
    float* yb = y + (size_t)b * T_ * H_;

    for (int t = 0; t < T_; t++) {
        float xv = __ldg(xpb + (size_t)t * G_);

        ull a0 = 0, a1 = 0, a2 = 0, a3 = 0;
        const ulonglong2* hp  = (const ulonglong2*)h_s;
        const ulonglong2* wp2 = (const ulonglong2*)wsrow;
        #pragma unroll
        for (int i = 0; i < 16; i++) {
            ulonglong2 hv = hp[i];
            a0 = fma2(w2[2*i],   hv.x, a0);
            a1 = fma2(w2[2*i+1], hv.y, a1);
        }
        #pragma unroll
        for (int i = 0; i < 16; i++) {
            ulonglong2 hv = hp[16 + i];
            ulonglong2 wv = wp2[i];
            a2 = fma2(wv.x, hv.x, a2);
            a3 = fma2(wv.y, hv.y, a3);
        }
        a0 = add2(a0, a1);
        a2 = add2(a2, a3);
        a0 = add2(a0, a2);
        float2 p = unpack2(a0);
        float raw = p.x + p.y + xv;

        float act;
        if (gtype == 2) act = tanhf(raw);
        else            act = 1.0f / (1.0f + __expf(-raw));
        gates_s[g] = act;
        __syncthreads();

        if (g < H_) {
            float iv = gates_s[g];
            float fv = gates_s[H_ + g];
            float gv = gates_s[2 * H_ + g];
            float ov = gates_s[3 * H_ + g];
            c = fv * c + iv * gv;
            float hnew = ov * tanhf(c);
            h_s[g] = hnew;
            yb[(size_t)t * H_ + g] = hnew;
        }
        __syncthreads();
    }

    if (g < H_) {
        hc_out[(size_t)layer * (B_ * H_) + b * H_ + g]       = h_s[g];
        hc_out[(size_t)(2 + layer) * (B_ * H_) + b * H_ + g] = c;
    }
}

// ---------------------------------------------------------------------------
// FC head via mma.sync (HMMA): logits = y1 @ fc_w^T + fc_b
// hi/lo bf16 split: acc = Ahi*Whi + Ahi*Wlo + Alo*Whi  (virtual K = 384)
// CTA tile 128x128, 8 warps (2x4) of 64x32, K-chunks of 64, 2-stage cp.async.
// smem: [128][72] bf16 per tile (pad 8 -> conflict-free ldmatrix), 2 stages.
// ---------------------------------------------------------------------------
#define FC_PAD    72                       // row stride in bf16 elems
#define FC_TILE_B (128 * FC_PAD * 2)       // 18432 bytes (one 128x64 tile)
#define FC_STAGE  (2 * FC_TILE_B)          // A + B per stage = 36864
#define FC_SMEM   (2 * FC_STAGE)           // 73728

__device__ __forceinline__ void fc_load_chunk(uint32_t sA, uint32_t sB,
    const __nv_bfloat16* __restrict__ Asrc, const __nv_bfloat16* __restrict__ Bsrc,
    int m0, int n0, int koff, int tid)
{
    #pragma unroll
    for (int it = 0; it < 4; it++) {
        int idx = tid + it * 256;          // 1024 x 16B for A
        int row = idx >> 3, c8 = idx & 7;
        cpasync16(sA + (uint32_t)(row * FC_PAD + c8 * 8) * 2,
                  Asrc + (size_t)(m0 + row) * H_ + koff + c8 * 8);
    }
    #pragma unroll
    for (int it = 0; it < 4; it++) {
        int idx = tid + it * 256;
        int row = idx >> 3, c8 = idx & 7;
        int gn = n0 + row; if (gn >= V_) gn = V_ - 1;   // clamp; those cols never stored
        cpasync16(sB + (uint32_t)(row * FC_PAD + c8 * 8) * 2,
                  Bsrc + (size_t)gn * H_ + koff + c8 * 8);
    }
}

__global__ __launch_bounds__(256, 2)
void fc_mma_kernel(const __nv_bfloat16* __restrict__ Ahi, const __nv_bfloat16* __restrict__ Alo,
                   const __nv_bfloat16* __restrict__ Whi, const __nv_bfloat16* __restrict__ Wlo,
                   const float* __restrict__ fcb, float* __restrict__ C)
{
    extern __shared__ char smem[];
    const uint32_t sbase = smem_u32(smem);
    const int tid  = threadIdx.x;
    const int wid  = tid >> 5, lane = tid & 31;
    const int wm   = wid >> 2;             // 0..1  -> m offset wm*64
    const int wn   = wid & 3;              // 0..3  -> n offset wn*32
    const int n0   = blockIdx.x * 128;
    const int m0   = blockIdx.y * 128;

    // ldmatrix lane-address offsets (bytes, relative to tile base)
    // A (x4 -> a0..a3 of m16k16): lanes 0-15: row=l, k=0 ; 16-31: row=l-16, k=8
    const uint32_t aRel = (uint32_t)(((wm * 64 + (lane & 15)) * FC_PAD + (lane >> 4) * 8) * 2);
    // B (x4 -> two n-frags): row = base + (l>>4)*8 + (l&7), k = ((l>>3)&1)*8
    const uint32_t bRel = (uint32_t)(FC_TILE_B +
        ((wn * 32 + (lane >> 4) * 8 + (lane & 7)) * FC_PAD + ((lane >> 3) & 1) * 8) * 2);

    const __nv_bfloat16* Aseg[3] = { Ahi, Ahi, Alo };
    const __nv_bfloat16* Bseg[3] = { Whi, Wlo, Whi };

    float acc[4][4][4];
    #pragma unroll
    for (int i = 0; i < 4; i++)
        #pragma unroll
        for (int j = 0; j < 4; j++)
            #pragma unroll
            for (int k = 0; k < 4; k++) acc[i][j][k] = 0.f;

    // prefetch chunk 0 (seg 0, koff 0) into stage 0
    fc_load_chunk(sbase, sbase + FC_TILE_B, Aseg[0], Bseg[0], m0, n0, 0, tid);
    CP_COMMIT();

    #pragma unroll
    for (int c = 0; c < 6; c++) {
        if (c + 1 < 6) {
            const int cn = c + 1;
            const uint32_t so = (uint32_t)(cn & 1) * FC_STAGE;
            fc_load_chunk(sbase + so, sbase + so + FC_TILE_B,
                          Aseg[cn >> 1], Bseg[cn >> 1], m0, n0, (cn & 1) * 64, tid);
            CP_COMMIT();
            CP_WAIT(1);               // oldest group (chunk c) is resident
        } else {
            CP_WAIT(0);
        }
        __syncthreads();

        const uint32_t so = (uint32_t)(c & 1) * FC_STAGE;
        const uint32_t aB = sbase + so + aRel;
        const uint32_t bB = sbase + so + bRel;
        #pragma unroll
        for (int k16 = 0; k16 < 4; k16++) {
            uint32_t a[4][4], b[4][2];
            #pragma unroll
            for (int mf = 0; mf < 4; mf++)
                ldsm_x4(a[mf][0], a[mf][1], a[mf][2], a[mf][3],
                        aB + mf * (16 * FC_PAD * 2) + k16 * 32);
            #pragma unroll
            for (int np = 0; np < 2; np++)
                ldsm_x4(b[2*np][0], b[2*np][1], b[2*np+1][0], b[2*np+1][1],
                        bB + np * (16 * FC_PAD * 2) + k16 * 32);
            #pragma unroll
            for (int mf = 0; mf < 4; mf++)
                #pragma unroll
                for (int nf = 0; nf < 4; nf++)
                    mma_bf16(acc[mf][nf], a[mf], b[nf]);
        }
        __syncthreads();
    }

    // epilogue: bias + store.
    // c-frag layout: c0,c1 -> row = lane>>2, cols 2*(lane&3)+{0,1}; c2,c3 -> row+8.
    // n is always even and V_ is even, so the float2 store never straddles V_.
    const int ncol = 2 * (lane & 3);
    const size_t rbase = (size_t)(m0 + wm * 64 + (lane >> 2));
    #pragma unroll
    for (int nf = 0; nf < 4; nf++) {
        const int n = n0 + wn * 32 + nf * 8 + ncol;
        if (n >= V_) continue;
        const float2 bv = *(const float2*)(fcb + n);
        #pragma unroll
        for (int mf = 0; mf < 4; mf++) {
            float* cp = C + (rbase + (size_t)mf * 16) * V_ + n;
            float2 o0 = make_float2(acc[mf][nf][0] + bv.x, acc[mf][nf][1] + bv.y);
            float2 o1 = make_float2(acc[mf][nf][2] + bv.x, acc[mf][nf][3] + bv.y);
            *(float2*)cp                    = o0;
            *(float2*)(cp + (size_t)8 * V_) = o1;
        }
    }
}

// ---------------------------------------------------------------------------
extern "C" void kernel_launch(void* const* d_in, const int* in_sizes, int n_in,
                              void* d_out, int out_size)
{
    const int*   x     = (const int*)  d_in[0];
    const float* emb   = (const float*)d_in[1];
    const float* W_ih0 = (const float*)d_in[2];
    const float* W_hh0 = (const float*)d_in[3];
    const float* b_ih0 = (const float*)d_in[4];
    const float* b_hh0 = (const float*)d_in[5];
    const float* W_ih1 = (const float*)d_in[6];
    const float* W_hh1 = (const float*)d_in[7];
    const float* b_ih1 = (const float*)d_in[8];
    const float* b_hh1 = (const float*)d_in[9];
    const float* fc_w  = (const float*)d_in[10];
    const float* fc_b  = (const float*)d_in[11];
    float* out = (float*)d_out;

    float *xp, *y0, *y1;
    __nv_bfloat16 *Whi, *Wlo, *Ahi, *Alo;
    cudaGetSymbolAddress((void**)&xp, g_xp);
    cudaGetSymbolAddress((void**)&y0, g_y0);
    cudaGetSymbolAddress((void**)&y1, g_y1);
    cudaGetSymbolAddress((void**)&Whi, g_Whi);
    cudaGetSymbolAddress((void**)&Wlo, g_Wlo);
    cudaGetSymbolAddress((void**)&Ahi, g_Ahi);
    cudaGetSymbolAddress((void**)&Alo, g_Alo);

    cudaFuncSetAttribute(lstm_kernel, cudaFuncAttributeMaxDynamicSharedMemorySize, LSTM_SMEM);
    cudaFuncSetAttribute(fc_mma_kernel, cudaFuncAttributeMaxDynamicSharedMemorySize, FC_SMEM);

    float* hc = out + (size_t)M_ * V_;   // logits, then h[2,B,H], c[2,B,H]

    // convert fc_w to bf16 hi/lo (overlaps the LSTM chain)
    {
        int n4 = (V_ * H_) / 4;
        cvt_hilo<<<(n4 + 255) / 256, 256>>>((const float4*)fc_w, (ushort4*)Whi, (ushort4*)Wlo, n4);
    }

    // Layer 0
    proj_kernel<true><<<dim3(G_/64, M_/64), 256>>>(nullptr, x, emb, W_ih0, b_ih0, b_hh0, xp);
    lstm_kernel<<<B_, 512, LSTM_SMEM>>>(xp, W_hh0, y0, hc, 0);

    // Layer 1
    proj_kernel<false><<<dim3(G_/64, M_/64), 256>>>(y0, nullptr, nullptr, W_ih1, b_ih1, b_hh1, xp);
    lstm_kernel<<<B_, 512, LSTM_SMEM>>>(xp, W_hh1, y1, hc, 1);

    // convert y1 to bf16 hi/lo
    {
        int n4 = (M_ * H_) / 4;
        cvt_hilo<<<(n4 + 255) / 256, 256>>>((const float4*)y1, (ushort4*)Ahi, (ushort4*)Alo, n4);
    }

    // Vocab projection on tensor cores (HMMA via mma.sync)
    fc_mma_kernel<<<dim3((V_ + 127) / 128, M_ / 128), 256, FC_SMEM>>>(Ahi, Alo, Whi, Wlo, fc_b, out);
}

// round 9
// speedup vs baseline: 2.6385x; 1.2044x over previous
#include <cuda_runtime.h>
#include <cuda_bf16.h>
#include <cstdint>

#define B_ 16
#define T_ 256
#define H_ 128
#define E_ 128
#define V_ 50000
#define G_ 512          // 4*H
#define M_ 4096         // B*T

typedef unsigned long long ull;

// ---------------- scratch (no cudaMalloc allowed) ----------------
__device__ float g_xp[M_ * G_];
__device__ float g_y0[M_ * H_];
__device__ float g_y1[M_ * H_];
__device__ __nv_bfloat16 g_Whi[(size_t)V_ * H_];
__device__ __nv_bfloat16 g_Wlo[(size_t)V_ * H_];
__device__ __nv_bfloat16 g_Ahi[M_ * H_];
__device__ __nv_bfloat16 g_Alo[M_ * H_];

// ---------------- f32x2 helpers ----------------
__device__ __forceinline__ ull fma2(ull a, ull b, ull c) {
    ull d; asm("fma.rn.f32x2 %0, %1, %2, %3;" : "=l"(d) : "l"(a), "l"(b), "l"(c)); return d;
}
__device__ __forceinline__ ull add2(ull a, ull b) {
    ull d; asm("add.rn.f32x2 %0, %1, %2;" : "=l"(d) : "l"(a), "l"(b)); return d;
}
__device__ __forceinline__ float2 unpack2(ull v) {
    float2 r; asm("mov.b64 {%0, %1}, %2;" : "=f"(r.x), "=f"(r.y) : "l"(v)); return r;
}

// ---------------- Ampere-path tensor helpers (valid on compute_103) --------
__device__ __forceinline__ uint32_t smem_u32(const void* p) {
    uint32_t a;
    asm("{ .reg .u64 t; cvta.to.shared.u64 t, %1; cvt.u32.u64 %0, t; }" : "=r"(a) : "l"(p));
    return a;
}
__device__ __forceinline__ void cpasync16(uint32_t dst, const void* src) {
    asm volatile("cp.async.cg.shared.global [%0], [%1], 16;" :: "r"(dst), "l"(src));
}
#define CP_COMMIT() asm volatile("cp.async.commit_group;" ::: "memory")
#define CP_WAIT(n)  asm volatile("cp.async.wait_group %0;" :: "n"(n) : "memory")

__device__ __forceinline__ void ldsm_x4(uint32_t& r0, uint32_t& r1, uint32_t& r2, uint32_t& r3,
                                        uint32_t addr) {
    asm volatile("ldmatrix.sync.aligned.m8n8.x4.shared.b16 {%0,%1,%2,%3}, [%4];"
                 : "=r"(r0), "=r"(r1), "=r"(r2), "=r"(r3) : "r"(addr));
}
__device__ __forceinline__ void mma_bf16(float* c, const uint32_t* a, const uint32_t* b) {
    asm volatile(
        "mma.sync.aligned.m16n8k16.row.col.f32.bf16.bf16.f32 "
        "{%0,%1,%2,%3}, {%4,%5,%6,%7}, {%8,%9}, {%0,%1,%2,%3};"
        : "+f"(c[0]), "+f"(c[1]), "+f"(c[2]), "+f"(c[3])
        : "r"(a[0]), "r"(a[1]), "r"(a[2]), "r"(a[3]), "r"(b[0]), "r"(b[1]));
}

// ---------------------------------------------------------------------------
// hi/lo bf16 split conversion (vectorized x4)
// ---------------------------------------------------------------------------
__global__ __launch_bounds__(256)
void cvt_hilo(const float4* __restrict__ src, ushort4* __restrict__ hi,
              ushort4* __restrict__ lo, int n4)
{
    int i = blockIdx.x * 256 + threadIdx.x;
    if (i >= n4) return;
    float4 v = src[i];
    ushort4 h, l;
    {
        __nv_bfloat16 hb;
        hb = __float2bfloat16(v.x); h.x = __bfloat16_as_ushort(hb);
        l.x = __bfloat16_as_ushort(__float2bfloat16(v.x - __bfloat162float(hb)));
        hb = __float2bfloat16(v.y); h.y = __bfloat16_as_ushort(hb);
        l.y = __bfloat16_as_ushort(__float2bfloat16(v.y - __bfloat162float(hb)));
        hb = __float2bfloat16(v.z); h.z = __bfloat16_as_ushort(hb);
        l.z = __bfloat16_as_ushort(__float2bfloat16(v.z - __bfloat162float(hb)));
        hb = __float2bfloat16(v.w); h.w = __bfloat16_as_ushort(hb);
        l.w = __bfloat16_as_ushort(__float2bfloat16(v.w - __bfloat162float(hb)));
    }
    hi[i] = h;
    lo[i] = l;
}

// ---------------------------------------------------------------------------
// Projection GEMM: C[M_,512] = A @ W^T + bias   (unchanged)
// ---------------------------------------------------------------------------
template<bool GATHER>
__global__ __launch_bounds__(256)
void proj_kernel(const float* __restrict__ A, const int* __restrict__ xidx,
                 const float* __restrict__ emb, const float* __restrict__ W,
                 const float* __restrict__ bia, const float* __restrict__ bib,
                 float* __restrict__ C)
{
    __shared__ float As[64][64];
    __shared__ float Bs[64][64];
    const int tid = threadIdx.x;
    const int tx = tid & 15, ty = tid >> 4;
    const int m0 = blockIdx.y * 64, n0 = blockIdx.x * 64;
    const int l  = tid & 63;
    const int kq = tid >> 6;

    const float* arow;
    if (GATHER) arow = emb + (size_t)xidx[m0 + l] * E_;
    else        arow = A   + (size_t)(m0 + l) * H_;
    const float* brow = W + (size_t)(n0 + l) * H_;

    float acc[4][4] = {};
    for (int kc = 0; kc < 128; kc += 64) {
        __syncthreads();
        #pragma unroll
        for (int it = 0; it < 4; it++) {
            int kb = kq * 4 + it * 16;
            float4 va = *(const float4*)(arow + kc + kb);
            As[kb+0][l] = va.x; As[kb+1][l] = va.y; As[kb+2][l] = va.z; As[kb+3][l] = va.w;
            float4 vb = *(const float4*)(brow + kc + kb);
            Bs[kb+0][l] = vb.x; Bs[kb+1][l] = vb.y; Bs[kb+2][l] = vb.z; Bs[kb+3][l] = vb.w;
        }
        __syncthreads();
        #pragma unroll 16
        for (int k = 0; k < 64; k++) {
            float4 a4 = *(const float4*)&As[k][ty * 4];
            float4 b4 = *(const float4*)&Bs[k][tx * 4];
            float av[4] = {a4.x, a4.y, a4.z, a4.w};
            float bv[4] = {b4.x, b4.y, b4.z, b4.w};
            #pragma unroll
            for (int i = 0; i < 4; i++)
                #pragma unroll
                for (int j = 0; j < 4; j++)
                    acc[i][j] = fmaf(av[i], bv[j], acc[i][j]);
        }
    }
    #pragma unroll
    for (int i = 0; i < 4; i++) {
        int m = m0 + ty * 4 + i;
        #pragma unroll
        for (int j = 0; j < 4; j++) {
            int n = n0 + tx * 4 + j;
            C[(size_t)m * G_ + n] = acc[i][j] + bia[n] + bib[n];
        }
    }
}

// ---------------------------------------------------------------------------
// LSTM recurrence, 2-CTA cluster per batch element.
// CTA rank r owns gate rows [r*256, r*256+256); each thread holds its full
// W_hh row (128 floats) in REGISTERS — zero smem W traffic.
// Per step: dot(h) -> act -> store act locally + to peer (st.shared::cluster)
// -> barrier.cluster (release/acquire) -> both CTAs redundantly update c,h
// (tid<128) -> __syncthreads. act double-buffered by step parity.
// ---------------------------------------------------------------------------
__global__ __launch_bounds__(256, 1) __cluster_dims__(2, 1, 1)
void lstm_kernel(const float* __restrict__ xp, const float* __restrict__ Whh,
                 float* __restrict__ y, float* __restrict__ hc_out, int layer)
{
    __shared__ float h_s[H_];
    __shared__ float act[2][G_];

    const int tid = threadIdx.x;
    uint32_t rank; asm("mov.u32 %0, %%cluster_ctarank;" : "=r"(rank));
    const int b  = blockIdx.x >> 1;
    const int gG = (int)rank * 256 + tid;     // global gate row 0..511
    const int gtype = gG >> 7;                // 0:i 1:f 2:g~ 3:o

    // Full W_hh row in registers (64 ull = 128 f32)
    ull w2[64];
    {
        const ulonglong2* wp = (const ulonglong2*)(Whh + (size_t)gG * H_);
        #pragma unroll
        for (int i = 0; i < 32; i++) { ulonglong2 v = wp[i]; w2[2*i] = v.x; w2[2*i+1] = v.y; }
    }

    // peer addresses for this thread's act slot (both parity buffers)
    const uint32_t peer = rank ^ 1u;
    uint32_t ra0, ra1;
    {
        uint32_t la0 = smem_u32(&act[0][gG]);
        uint32_t la1 = smem_u32(&act[1][gG]);
        asm("mapa.shared::cluster.u32 %0, %1, %2;" : "=r"(ra0) : "r"(la0), "r"(peer));
        asm("mapa.shared::cluster.u32 %0, %1, %2;" : "=r"(ra1) : "r"(la1), "r"(peer));
    }

    float c = 0.f;
    if (tid < H_) h_s[tid] = 0.f;
    __syncthreads();                          // h_s init (local readers only)

    const float* xpb = xp + (size_t)b * T_ * G_ + gG;
    float* yb = y + (size_t)b * T_ * H_;

    for (int t = 0; t < T_; t++) {
        float xv = __ldg(xpb + (size_t)t * G_);   // issued early, used late

        // dot: h_s (broadcast LDS) x W-row (registers), 4 independent chains
        ull a0 = 0, a1 = 0, a2 = 0, a3 = 0;
        const ulonglong2* hp = (const ulonglong2*)h_s;
        #pragma unroll
        for (int i = 0; i < 32; i++) {
            ulonglong2 hv = hp[i];
            if (i & 1) { a2 = fma2(w2[2*i], hv.x, a2); a3 = fma2(w2[2*i+1], hv.y, a3); }
            else       { a0 = fma2(w2[2*i], hv.x, a0); a1 = fma2(w2[2*i+1], hv.y, a1); }
        }
        a0 = add2(a0, a2); a1 = add2(a1, a3); a0 = add2(a0, a1);
        float2 pr = unpack2(a0);
        float raw = pr.x + pr.y + xv;

        float a = (gtype == 2) ? tanhf(raw) : (1.0f / (1.0f + __expf(-raw)));

        const int p = t & 1;
        act[p][gG] = a;                               // local copy
        asm volatile("st.shared::cluster.f32 [%0], %1;"
                     :: "r"(p ? ra1 : ra0), "f"(a));  // peer copy

        asm volatile("barrier.cluster.arrive.aligned;" ::: "memory");
        asm volatile("barrier.cluster.wait.aligned;"   ::: "memory");

        if (tid < H_) {                               // redundant in both CTAs
            float iv = act[p][tid];
            float fv = act[p][H_ + tid];
            float gv = act[p][2 * H_ + tid];
            float ov = act[p][3 * H_ + tid];
            c = fv * c + iv * gv;
            float hnew = ov * tanhf(c);
            h_s[tid] = hnew;
            if (rank == 0) yb[(size_t)t * H_ + tid] = hnew;
        }
        __syncthreads();                              // h_s ready for next dot
    }

    if (rank == 0 && tid < H_) {
        hc_out[(size_t)layer * (B_ * H_) + b * H_ + tid]       = h_s[tid];
        hc_out[(size_t)(2 + layer) * (B_ * H_) + b * H_ + tid] = c;
    }
}

// ---------------------------------------------------------------------------
// FC head via mma.sync (HMMA): logits = y1 @ fc_w^T + fc_b
// hi/lo bf16 split: acc = Ahi*Whi + Ahi*Wlo + Alo*Whi  (virtual K = 384)
// Only 4 distinct A tiles and 4 distinct B tiles exist across the 6 chunks:
// A tiles (Ahi-k0, Ahi-k64, Alo-k0, Alo-k64) are RESIDENT (loaded once);
// B tiles stream through a 2-stage buffer (chunk seq: Whi-k0, Whi-k64,
// Wlo-k0, Wlo-k64, Whi-k0, Whi-k64 — the repeats hit L2).
// smem: 4*18432 (A) + 2*18432 (B) = 110592 -> 2 CTAs/SM.
// ---------------------------------------------------------------------------
#define FC_PAD    72                        // row stride in bf16 elems
#define FC_TILE   (128 * FC_PAD * 2)        // 18432 bytes per 128x64 tile
#define FC_BBASE  (4 * FC_TILE)             // B region offset
#define FC_SMEM   (FC_BBASE + 2 * FC_TILE)  // 110592

__device__ __forceinline__ void fc_load_A(uint32_t dst,
    const __nv_bfloat16* __restrict__ src, int m0, int koff, int tid)
{
    #pragma unroll
    for (int it = 0; it < 4; it++) {
        int idx = tid + it * 256;
        int row = idx >> 3, c8 = idx & 7;
        cpasync16(dst + (uint32_t)(row * FC_PAD + c8 * 8) * 2,
                  src + (size_t)(m0 + row) * H_ + koff + c8 * 8);
    }
}
__device__ __forceinline__ void fc_load_B(uint32_t dst,
    const __nv_bfloat16* __restrict__ src, int n0, int koff, int tid)
{
    #pragma unroll
    for (int it = 0; it < 4; it++) {
        int idx = tid + it * 256;
        int row = idx >> 3, c8 = idx & 7;
        int gn = n0 + row; if (gn >= V_) gn = V_ - 1;   // clamp; never stored
        cpasync16(dst + (uint32_t)(row * FC_PAD + c8 * 8) * 2,
                  src + (size_t)gn * H_ + koff + c8 * 8);
    }
}

__global__ __launch_bounds__(256, 2)
void fc_mma_kernel(const __nv_bfloat16* __restrict__ Ahi, const __nv_bfloat16* __restrict__ Alo,
                   const __nv_bfloat16* __restrict__ Whi, const __nv_bfloat16* __restrict__ Wlo,
                   const float* __restrict__ fcb, float* __restrict__ C)
{
    extern __shared__ char smem[];
    const uint32_t sbase = smem_u32(smem);
    const int tid  = threadIdx.x;
    const int wid  = tid >> 5, lane = tid & 31;
    const int wm   = wid >> 2;             // 0..1  -> m offset wm*64
    const int wn   = wid & 3;              // 0..3  -> n offset wn*32
    const int n0   = blockIdx.x * 128;
    const int m0   = blockIdx.y * 128;

    // ldmatrix lane-address offsets (bytes, within a tile)
    const uint32_t aRel = (uint32_t)(((wm * 64 + (lane & 15)) * FC_PAD + (lane >> 4) * 8) * 2);
    const uint32_t bRel = (uint32_t)(
        ((wn * 32 + (lane >> 4) * 8 + (lane & 7)) * FC_PAD + ((lane >> 3) & 1) * 8) * 2);

    float acc[4][4][4];
    #pragma unroll
    for (int i = 0; i < 4; i++)
        #pragma unroll
        for (int j = 0; j < 4; j++)
            #pragma unroll
            for (int k = 0; k < 4; k++) acc[i][j][k] = 0.f;

    // prologue: resident A tiles + B chunk 0, then B chunk 1
    fc_load_A(sbase + 0 * FC_TILE, Ahi, m0, 0,  tid);
    fc_load_A(sbase + 1 * FC_TILE, Ahi, m0, 64, tid);
    fc_load_A(sbase + 2 * FC_TILE, Alo, m0, 0,  tid);
    fc_load_A(sbase + 3 * FC_TILE, Alo, m0, 64, tid);
    fc_load_B(sbase + FC_BBASE + 0 * FC_TILE, Whi, n0, 0, tid);
    CP_COMMIT();                                        // G0 = {A x4, B0}
    fc_load_B(sbase + FC_BBASE + 1 * FC_TILE, Whi, n0, 64, tid);
    CP_COMMIT();                                        // G1 = {B1}

    // chunk c: A tile At[c], B source Bp[c] at koff Bk[c], B stage c&1
    #pragma unroll
    for (int c = 0; c < 6; c++) {
        const int At[6] = {0, 1, 0, 1, 2, 3};
        if (c < 5) { CP_WAIT(1); } else { CP_WAIT(0); }
        __syncthreads();

        const uint32_t aB = sbase + (uint32_t)At[c] * FC_TILE + aRel;
        const uint32_t bB = sbase + FC_BBASE + (uint32_t)(c & 1) * FC_TILE + bRel;
        #pragma unroll
        for (int k16 = 0; k16 < 4; k16++) {
            uint32_t a[4][4], b[4][2];
            #pragma unroll
            for (int mf = 0; mf < 4; mf++)
                ldsm_x4(a[mf][0], a[mf][1], a[mf][2], a[mf][3],
                        aB + mf * (16 * FC_PAD * 2) + k16 * 32);
            #pragma unroll
            for (int np = 0; np < 2; np++)
                ldsm_x4(b[2*np][0], b[2*np][1], b[2*np+1][0], b[2*np+1][1],
                        bB + np * (16 * FC_PAD * 2) + k16 * 32);
            #pragma unroll
            for (int mf = 0; mf < 4; mf++)
                #pragma unroll
                for (int nf = 0; nf < 4; nf++)
                    mma_bf16(acc[mf][nf], a[mf], b[nf]);
        }
        __syncthreads();                    // stage (c&1) free for reuse

        if (c + 2 <= 5) {                   // prefetch B(c+2) into stage c&1
            const __nv_bfloat16* Bp = (c + 2 == 2 || c + 2 == 3) ? Wlo : Whi;
            const int Bk = ((c + 2) & 1) * 64;
            fc_load_B(sbase + FC_BBASE + (uint32_t)(c & 1) * FC_TILE, Bp, n0, Bk, tid);
            CP_COMMIT();
        }
    }

    // epilogue: bias + store (mapping verified in R8; n even, V_ even)
    const int ncol = 2 * (lane & 3);
    const size_t rbase = (size_t)(m0 + wm * 64 + (lane >> 2));
    #pragma unroll
    for (int nf = 0; nf < 4; nf++) {
        const int n = n0 + wn * 32 + nf * 8 + ncol;
        if (n >= V_) continue;
        const float2 bv = *(const float2*)(fcb + n);
        #pragma unroll
        for (int mf = 0; mf < 4; mf++) {
            float* cp = C + (rbase + (size_t)mf * 16) * V_ + n;
            float2 o0 = make_float2(acc[mf][nf][0] + bv.x, acc[mf][nf][1] + bv.y);
            float2 o1 = make_float2(acc[mf][nf][2] + bv.x, acc[mf][nf][3] + bv.y);
            *(float2*)cp                    = o0;
            *(float2*)(cp + (size_t)8 * V_) = o1;
        }
    }
}

// ---------------------------------------------------------------------------
extern "C" void kernel_launch(void* const* d_in, const int* in_sizes, int n_in,
                              void* d_out, int out_size)
{
    const int*   x     = (const int*)  d_in[0];
    const float* emb   = (const float*)d_in[1];
    const float* W_ih0 = (const float*)d_in[2];
    const float* W_hh0 = (const float*)d_in[3];
    const float* b_ih0 = (const float*)d_in[4];
    const float* b_hh0 = (const float*)d_in[5];
    const float* W_ih1 = (const float*)d_in[6];
    const float* W_hh1 = (const float*)d_in[7];
    const float* b_ih1 = (const float*)d_in[8];
    const float* b_hh1 = (const float*)d_in[9];
    const float* fc_w  = (const float*)d_in[10];
    const float* fc_b  = (const float*)d_in[11];
    float* out = (float*)d_out;

    float *xp, *y0, *y1;
    __nv_bfloat16 *Whi, *Wlo, *Ahi, *Alo;
    cudaGetSymbolAddress((void**)&xp, g_xp);
    cudaGetSymbolAddress((void**)&y0, g_y0);
    cudaGetSymbolAddress((void**)&y1, g_y1);
    cudaGetSymbolAddress((void**)&Whi, g_Whi);
    cudaGetSymbolAddress((void**)&Wlo, g_Wlo);
    cudaGetSymbolAddress((void**)&Ahi, g_Ahi);
    cudaGetSymbolAddress((void**)&Alo, g_Alo);

    cudaFuncSetAttribute(fc_mma_kernel, cudaFuncAttributeMaxDynamicSharedMemorySize, FC_SMEM);

    float* hc = out + (size_t)M_ * V_;   // logits, then h[2,B,H], c[2,B,H]

    // convert fc_w to bf16 hi/lo (overlaps the LSTM chain)
    {
        int n4 = (V_ * H_) / 4;
        cvt_hilo<<<(n4 + 255) / 256, 256>>>((const float4*)fc_w, (ushort4*)Whi, (ushort4*)Wlo, n4);
    }

    // Layer 0
    proj_kernel<true><<<dim3(G_/64, M_/64), 256>>>(nullptr, x, emb, W_ih0, b_ih0, b_hh0, xp);
    lstm_kernel<<<2 * B_, 256>>>(xp, W_hh0, y0, hc, 0);

    // Layer 1
    proj_kernel<false><<<dim3(G_/64, M_/64), 256>>>(y0, nullptr, nullptr, W_ih1, b_ih1, b_hh1, xp);
    lstm_kernel<<<2 * B_, 256>>>(xp, W_hh1, y1, hc, 1);

    // convert y1 to bf16 hi/lo
    {
        int n4 = (M_ * H_) / 4;
        cvt_hilo<<<(n4 + 255) / 256, 256>>>((const float4*)y1, (ushort4*)Ahi, (ushort4*)Alo, n4);
    }

    // Vocab projection on tensor cores (HMMA via mma.sync)
    fc_mma_kernel<<<dim3((V_ + 127) / 128, M_ / 128), 256, FC_SMEM>>>(Ahi, Alo, Whi, Wlo, fc_b, out);
}